// round 2
// baseline (speedup 1.0000x reference)
#include <cuda_runtime.h>
#include <cuda_bf16.h>
#include <mma.h>

using namespace nvcuda;

// Problem constants
constexpr int T_ = 4;
constexpr int B_ = 16;
constexpr int C_ = 512;
constexpr int N_ = 256;                // H*W
constexpr int S_ = B_ * C_ * N_;       // per-timestep elements = 2,097,152
constexpr int TOT_ = T_ * S_;          // 8,388,608

// Scratch (device globals: allocation-free rule)
__device__ float g_wq[C_ * C_];
__device__ float g_wk[C_ * C_];
__device__ float g_wv[C_ * C_];
__device__ float g_wp[C_ * C_];
__device__ float g_sq[C_];
__device__ float g_sk[C_];
__device__ float g_sv[C_];
__device__ float g_sp[C_];
__device__ float g_xs[TOT_];
__device__ float g_q[TOT_];
__device__ float g_k[TOT_];
__device__ float g_v[TOT_];
__device__ float g_kvs[T_ * B_ * C_];

// ---------------------------------------------------------------------------
// Prep: fold BN scale into weights; compute per-channel shifts.
// ---------------------------------------------------------------------------
__global__ void prep_kernel(
    const float* __restrict__ qw, const float* __restrict__ qg, const float* __restrict__ qb,
    const float* __restrict__ qm, const float* __restrict__ qvv,
    const float* __restrict__ kw, const float* __restrict__ kg, const float* __restrict__ kb,
    const float* __restrict__ km, const float* __restrict__ kvv,
    const float* __restrict__ vw, const float* __restrict__ vg, const float* __restrict__ vb,
    const float* __restrict__ vm, const float* __restrict__ vvv,
    const float* __restrict__ pw, const float* __restrict__ pb, const float* __restrict__ pg,
    const float* __restrict__ pb2, const float* __restrict__ pm, const float* __restrict__ pvv)
{
    int idx = blockIdx.x * blockDim.x + threadIdx.x;
    if (idx >= C_ * C_) return;
    int o = idx >> 9;
    float invq = qg[o] / sqrtf(qvv[o] + 1e-5f);
    float invk = kg[o] / sqrtf(kvv[o] + 1e-5f);
    float invv = vg[o] / sqrtf(vvv[o] + 1e-5f);
    float invp = pg[o] / sqrtf(pvv[o] + 1e-5f);
    g_wq[idx] = qw[idx] * invq;
    g_wk[idx] = kw[idx] * invk;
    g_wv[idx] = vw[idx] * invv;
    g_wp[idx] = pw[idx] * invp;
    if ((idx & 511) == 0) {
        g_sq[o] = qb[o] - qm[o] * invq;
        g_sk[o] = kb[o] - km[o] * invk;
        g_sv[o] = vb[o] - vm[o] * invv;
        g_sp[o] = (pb[o] - pm[o]) * invp + pb2[o];
    }
}

// ---------------------------------------------------------------------------
// LIF on input x -> binary spikes xs.  v' = v + (x - v)/2; s = v'>=1; reset.
// ---------------------------------------------------------------------------
__global__ void lif_x_kernel(const float* __restrict__ x)
{
    int i = blockIdx.x * blockDim.x + threadIdx.x;
    if (i >= S_) return;
    float v = 0.f;
#pragma unroll
    for (int t = 0; t < T_; t++) {
        float xv = x[t * S_ + i];
        v = v + (xv - v) * 0.5f;
        float s = (v >= 1.0f) ? 1.f : 0.f;
        g_xs[t * S_ + i] = s;
        v = v * (1.f - s);
    }
}

// ---------------------------------------------------------------------------
// LIF on q/k/v pre-activations (+ folded BN shift), in place -> spikes.
// ---------------------------------------------------------------------------
__global__ void lif_qkv_kernel()
{
    int i = blockIdx.x * blockDim.x + threadIdx.x;
    if (i >= S_) return;
    int which = blockIdx.y;
    float* buf = (which == 0) ? g_q : (which == 1) ? g_k : g_v;
    const float* sh = (which == 0) ? g_sq : (which == 1) ? g_sk : g_sv;
    int c = (i >> 8) & (C_ - 1);   // i = b*C*N + c*N + n, N=256
    float shift = sh[c];
    float v = 0.f;
#pragma unroll
    for (int t = 0; t < T_; t++) {
        float pre = buf[t * S_ + i] + shift;
        v = v + (pre - v) * 0.5f;
        float s = (v >= 1.0f) ? 1.f : 0.f;
        buf[t * S_ + i] = s;
        v = v * (1.f - s);
    }
}

// ---------------------------------------------------------------------------
// kv = sum_n k*v per (t,b,c)  (exact integers), then LIF with v_th=0.5.
// One warp per (b,c); sequential over t.
// ---------------------------------------------------------------------------
__global__ void kv_kernel()
{
    int gw = (blockIdx.x * blockDim.x + threadIdx.x) >> 5;
    int lane = threadIdx.x & 31;
    if (gw >= B_ * C_) return;      // gw = b*C + c
    float v = 0.f;
#pragma unroll
    for (int t = 0; t < T_; t++) {
        const float* kp = g_k + t * S_ + gw * N_;
        const float* vp = g_v + t * S_ + gw * N_;
        float sum = 0.f;
#pragma unroll
        for (int j = 0; j < N_ / 32; j++)
            sum += kp[lane + j * 32] * vp[lane + j * 32];
#pragma unroll
        for (int off = 16; off > 0; off >>= 1)
            sum += __shfl_xor_sync(0xFFFFFFFFu, sum, off);
        v = v + (sum - v) * 0.5f;
        float s = (v >= 0.5f) ? 1.f : 0.f;
        if (lane == 0) g_kvs[t * B_ * C_ + gw] = s;
        v = v * (1.f - s);
    }
}

// ---------------------------------------------------------------------------
// tf32 wmma GEMM: Y[o][n] = sum_c A[o][c] * X[c][n]
// MODE 0: A in {g_wq,g_wk,g_wv} (z = which*64 + tb), X = xs, out raw to g_q/g_k/g_v
// MODE 1: A = g_wp, X = q * kvs (attn, built in the loader),
//         epilogue adds g_sp[o] + identity, writes d_out.
// Tile: 64x64x32, 4 warps (each 32x32 via 2x2 m16n16k8 fragments).
// ---------------------------------------------------------------------------
constexpr int BM = 64, BN = 64, BK = 32;
constexpr int ASTR = BK + 4;   // 36
constexpr int BSTR = BN + 4;   // 68

template <int MODE>
__global__ void __launch_bounds__(128) gemm_kernel(const float* __restrict__ x_identity,
                                                   float* __restrict__ out_global)
{
    __shared__ float smem[BM * ASTR + BK * BSTR];   // 4480 floats
    float* As = smem;
    float* Bs = smem + BM * ASTR;

    int tid = threadIdx.x;
    int warp = tid >> 5;
    int wr = warp >> 1, wc = warp & 1;
    int n0 = blockIdx.x * BN;
    int o0 = blockIdx.y * BM;
    int z = blockIdx.z;

    const float* A;
    const float* Bsrc;
    float* Cdst = nullptr;
    const float* kvs = nullptr;
    int tb;
    if (MODE == 0) {
        int which = z >> 6;
        tb = z & 63;
        A = (which == 0) ? g_wq : (which == 1) ? g_wk : g_wv;
        Bsrc = g_xs + (size_t)tb * C_ * N_;
        Cdst = ((which == 0) ? g_q : (which == 1) ? g_k : g_v) + (size_t)tb * C_ * N_;
    } else {
        tb = z;
        A = g_wp;
        Bsrc = g_q + (size_t)tb * C_ * N_;
        kvs = g_kvs + tb * C_;
    }

    wmma::fragment<wmma::accumulator, 16, 16, 8, float> acc[2][2];
#pragma unroll
    for (int i = 0; i < 2; i++)
#pragma unroll
        for (int j = 0; j < 2; j++)
            wmma::fill_fragment(acc[i][j], 0.0f);

    for (int kt = 0; kt < C_; kt += BK) {
        // A tile: 64 rows x 32 cols (512 float4 / 128 threads = 4 each)
#pragma unroll
        for (int i = 0; i < 4; i++) {
            int idx = tid + i * 128;
            int r = idx >> 3;
            int c4 = (idx & 7) << 2;
            float4 vv = *reinterpret_cast<const float4*>(&A[(o0 + r) * C_ + kt + c4]);
            *reinterpret_cast<float4*>(&As[r * ASTR + c4]) = vv;
        }
        // B tile: 32 rows x 64 cols
#pragma unroll
        for (int i = 0; i < 4; i++) {
            int idx = tid + i * 128;
            int r = idx >> 4;
            int c4 = (idx & 15) << 2;
            float4 vv = *reinterpret_cast<const float4*>(&Bsrc[(kt + r) * N_ + n0 + c4]);
            if (MODE == 1) {
                float s = kvs[kt + r];
                vv.x *= s; vv.y *= s; vv.z *= s; vv.w *= s;
            }
            *reinterpret_cast<float4*>(&Bs[r * BSTR + c4]) = vv;
        }
        __syncthreads();

#pragma unroll
        for (int kk = 0; kk < BK; kk += 8) {
            wmma::fragment<wmma::matrix_a, 16, 16, 8, wmma::precision::tf32, wmma::row_major> af[2];
            wmma::fragment<wmma::matrix_b, 16, 16, 8, wmma::precision::tf32, wmma::row_major> bf[2];
#pragma unroll
            for (int i = 0; i < 2; i++) {
                wmma::load_matrix_sync(af[i], &As[(wr * 32 + i * 16) * ASTR + kk], ASTR);
#pragma unroll
                for (int e = 0; e < af[i].num_elements; e++)
                    af[i].x[e] = wmma::__float_to_tf32(af[i].x[e]);
            }
#pragma unroll
            for (int j = 0; j < 2; j++) {
                wmma::load_matrix_sync(bf[j], &Bs[kk * BSTR + wc * 32 + j * 16], BSTR);
#pragma unroll
                for (int e = 0; e < bf[j].num_elements; e++)
                    bf[j].x[e] = wmma::__float_to_tf32(bf[j].x[e]);
            }
#pragma unroll
            for (int i = 0; i < 2; i++)
#pragma unroll
                for (int j = 0; j < 2; j++)
                    wmma::mma_sync(acc[i][j], af[i], bf[j], acc[i][j]);
        }
        __syncthreads();
    }

    if (MODE == 0) {
#pragma unroll
        for (int i = 0; i < 2; i++)
#pragma unroll
            for (int j = 0; j < 2; j++)
                wmma::store_matrix_sync(&Cdst[(o0 + wr * 32 + i * 16) * N_ + n0 + wc * 32 + j * 16],
                                        acc[i][j], N_, wmma::mem_row_major);
    } else {
        // stage through smem, add shift + identity, write output
        float* Cs = smem;   // 64 x BSTR <= 4480 floats
#pragma unroll
        for (int i = 0; i < 2; i++)
#pragma unroll
            for (int j = 0; j < 2; j++)
                wmma::store_matrix_sync(&Cs[(wr * 32 + i * 16) * BSTR + wc * 32 + j * 16],
                                        acc[i][j], BSTR, wmma::mem_row_major);
        __syncthreads();
        const float* xid = x_identity + (size_t)tb * C_ * N_;
        float* outp = out_global + (size_t)tb * C_ * N_;
#pragma unroll
        for (int e = 0; e < 8; e++) {
            int idx = tid + e * 128;      // 0..1023 (1024 float4 = 4096 elems)
            int r = idx >> 4;
            int c4 = (idx & 15) << 2;
            int o = o0 + r;
            float4 cv = *reinterpret_cast<const float4*>(&Cs[r * BSTR + c4]);
            float4 xv = *reinterpret_cast<const float4*>(&xid[o * N_ + n0 + c4]);
            float sp = g_sp[o];
            float4 res;
            res.x = cv.x + sp + xv.x;
            res.y = cv.y + sp + xv.y;
            res.z = cv.z + sp + xv.z;
            res.w = cv.w + sp + xv.w;
            *reinterpret_cast<float4*>(&outp[o * N_ + n0 + c4]) = res;
        }
    }
}

// ---------------------------------------------------------------------------
extern "C" void kernel_launch(void* const* d_in, const int* in_sizes, int n_in,
                              void* d_out, int out_size)
{
    const float* x    = (const float*)d_in[0];
    const float* q_w  = (const float*)d_in[1];
    const float* q_g  = (const float*)d_in[2];
    const float* q_b  = (const float*)d_in[3];
    const float* q_m  = (const float*)d_in[4];
    const float* q_v  = (const float*)d_in[5];
    const float* k_w  = (const float*)d_in[6];
    const float* k_g  = (const float*)d_in[7];
    const float* k_b  = (const float*)d_in[8];
    const float* k_m  = (const float*)d_in[9];
    const float* k_v  = (const float*)d_in[10];
    const float* v_w  = (const float*)d_in[11];
    const float* v_g  = (const float*)d_in[12];
    const float* v_b  = (const float*)d_in[13];
    const float* v_m  = (const float*)d_in[14];
    const float* v_v  = (const float*)d_in[15];
    const float* p_w  = (const float*)d_in[16];
    const float* p_b  = (const float*)d_in[17];
    const float* p_g  = (const float*)d_in[18];
    const float* p_b2 = (const float*)d_in[19];
    const float* p_m  = (const float*)d_in[20];
    const float* p_v  = (const float*)d_in[21];
    float* out = (float*)d_out;

    prep_kernel<<<(C_ * C_ + 255) / 256, 256>>>(
        q_w, q_g, q_b, q_m, q_v,
        k_w, k_g, k_b, k_m, k_v,
        v_w, v_g, v_b, v_m, v_v,
        p_w, p_b, p_g, p_b2, p_m, p_v);

    lif_x_kernel<<<(S_ + 255) / 256, 256>>>(x);

    gemm_kernel<0><<<dim3(N_ / BN, C_ / BM, 3 * T_ * B_), 128>>>(nullptr, nullptr);

    lif_qkv_kernel<<<dim3((S_ + 255) / 256, 3), 256>>>();

    kv_kernel<<<(B_ * C_ * 32 + 255) / 256, 256>>>();

    gemm_kernel<1><<<dim3(N_ / BN, C_ / BM, T_ * B_), 128>>>(x, out);
}

// round 3
// speedup vs baseline: 1.0001x; 1.0001x over previous
#include <cuda_runtime.h>
#include <cuda_bf16.h>
#include <mma.h>

using namespace nvcuda;

// Problem constants
constexpr int T_ = 4;
constexpr int B_ = 16;
constexpr int C_ = 512;
constexpr int N_ = 256;                // H*W
constexpr int S_ = B_ * C_ * N_;       // per-timestep elements = 2,097,152
constexpr int TOT_ = T_ * S_;          // 8,388,608

// Scratch (device globals: allocation-free rule)
__device__ float g_wq[C_ * C_];
__device__ float g_wk[C_ * C_];
__device__ float g_wv[C_ * C_];
__device__ float g_wp[C_ * C_];
__device__ float g_sq[C_];
__device__ float g_sk[C_];
__device__ float g_sv[C_];
__device__ float g_sp[C_];
__device__ float g_xs[TOT_];
__device__ float g_q[TOT_];
__device__ float g_k[TOT_];
__device__ float g_v[TOT_];
__device__ float g_kvs[T_ * B_ * C_];

// ---------------------------------------------------------------------------
// Prep: fold BN scale into weights; compute per-channel shifts.
// ---------------------------------------------------------------------------
__global__ void prep_kernel(
    const float* __restrict__ qw, const float* __restrict__ qg, const float* __restrict__ qb,
    const float* __restrict__ qm, const float* __restrict__ qvv,
    const float* __restrict__ kw, const float* __restrict__ kg, const float* __restrict__ kb,
    const float* __restrict__ km, const float* __restrict__ kvv,
    const float* __restrict__ vw, const float* __restrict__ vg, const float* __restrict__ vb,
    const float* __restrict__ vm, const float* __restrict__ vvv,
    const float* __restrict__ pw, const float* __restrict__ pb, const float* __restrict__ pg,
    const float* __restrict__ pb2, const float* __restrict__ pm, const float* __restrict__ pvv)
{
    int idx = blockIdx.x * blockDim.x + threadIdx.x;
    if (idx >= C_ * C_) return;
    int o = idx >> 9;
    float invq = qg[o] / sqrtf(qvv[o] + 1e-5f);
    float invk = kg[o] / sqrtf(kvv[o] + 1e-5f);
    float invv = vg[o] / sqrtf(vvv[o] + 1e-5f);
    float invp = pg[o] / sqrtf(pvv[o] + 1e-5f);
    g_wq[idx] = qw[idx] * invq;
    g_wk[idx] = kw[idx] * invk;
    g_wv[idx] = vw[idx] * invv;
    g_wp[idx] = pw[idx] * invp;
    if ((idx & 511) == 0) {
        g_sq[o] = qb[o] - qm[o] * invq;
        g_sk[o] = kb[o] - km[o] * invk;
        g_sv[o] = vb[o] - vm[o] * invv;
        g_sp[o] = (pb[o] - pm[o]) * invp + pb2[o];
    }
}

// ---------------------------------------------------------------------------
// LIF on input x -> binary spikes xs.  v' = v + (x - v)/2; s = v'>=1; reset.
// ---------------------------------------------------------------------------
__global__ void lif_x_kernel(const float* __restrict__ x)
{
    int i = blockIdx.x * blockDim.x + threadIdx.x;
    if (i >= S_) return;
    float v = 0.f;
#pragma unroll
    for (int t = 0; t < T_; t++) {
        float xv = x[t * S_ + i];
        v = v + (xv - v) * 0.5f;
        float s = (v >= 1.0f) ? 1.f : 0.f;
        g_xs[t * S_ + i] = s;
        v = v * (1.f - s);
    }
}

// ---------------------------------------------------------------------------
// LIF on q/k/v pre-activations (+ folded BN shift), in place -> spikes.
// ---------------------------------------------------------------------------
__global__ void lif_qkv_kernel()
{
    int i = blockIdx.x * blockDim.x + threadIdx.x;
    if (i >= S_) return;
    int which = blockIdx.y;
    float* buf = (which == 0) ? g_q : (which == 1) ? g_k : g_v;
    const float* sh = (which == 0) ? g_sq : (which == 1) ? g_sk : g_sv;
    int c = (i >> 8) & (C_ - 1);   // i = b*C*N + c*N + n, N=256
    float shift = sh[c];
    float v = 0.f;
#pragma unroll
    for (int t = 0; t < T_; t++) {
        float pre = buf[t * S_ + i] + shift;
        v = v + (pre - v) * 0.5f;
        float s = (v >= 1.0f) ? 1.f : 0.f;
        buf[t * S_ + i] = s;
        v = v * (1.f - s);
    }
}

// ---------------------------------------------------------------------------
// kv = sum_n k*v per (t,b,c)  (exact integers), then LIF with v_th=0.5.
// One warp per (b,c); sequential over t.
// ---------------------------------------------------------------------------
__global__ void kv_kernel()
{
    int gw = (blockIdx.x * blockDim.x + threadIdx.x) >> 5;
    int lane = threadIdx.x & 31;
    if (gw >= B_ * C_) return;      // gw = b*C + c
    float v = 0.f;
#pragma unroll
    for (int t = 0; t < T_; t++) {
        const float* kp = g_k + t * S_ + gw * N_;
        const float* vp = g_v + t * S_ + gw * N_;
        float sum = 0.f;
#pragma unroll
        for (int j = 0; j < N_ / 32; j++)
            sum += kp[lane + j * 32] * vp[lane + j * 32];
#pragma unroll
        for (int off = 16; off > 0; off >>= 1)
            sum += __shfl_xor_sync(0xFFFFFFFFu, sum, off);
        v = v + (sum - v) * 0.5f;
        float s = (v >= 0.5f) ? 1.f : 0.f;
        if (lane == 0) g_kvs[t * B_ * C_ + gw] = s;
        v = v * (1.f - s);
    }
}

// ---------------------------------------------------------------------------
// tf32 wmma GEMM: Y[o][n] = sum_c A[o][c] * X[c][n]
// MODE 0: A in {g_wq,g_wk,g_wv} (z = which*64 + tb), X = xs, out raw to g_q/g_k/g_v
// MODE 1: A = g_wp, X = q * kvs (attn, built in the loader),
//         epilogue adds g_sp[o] + identity, writes d_out.
// Tile: 64x64x32, 4 warps (each 32x32 via 2x2 m16n16k8 fragments).
// ---------------------------------------------------------------------------
constexpr int BM = 64, BN = 64, BK = 32;
constexpr int ASTR = BK + 4;   // 36
constexpr int BSTR = BN + 4;   // 68

template <int MODE>
__global__ void __launch_bounds__(128) gemm_kernel(const float* __restrict__ x_identity,
                                                   float* __restrict__ out_global)
{
    __shared__ float smem[BM * ASTR + BK * BSTR];   // 4480 floats
    float* As = smem;
    float* Bs = smem + BM * ASTR;

    int tid = threadIdx.x;
    int warp = tid >> 5;
    int wr = warp >> 1, wc = warp & 1;
    int n0 = blockIdx.x * BN;
    int o0 = blockIdx.y * BM;
    int z = blockIdx.z;

    const float* A;
    const float* Bsrc;
    float* Cdst = nullptr;
    const float* kvs = nullptr;
    int tb;
    if (MODE == 0) {
        int which = z >> 6;
        tb = z & 63;
        A = (which == 0) ? g_wq : (which == 1) ? g_wk : g_wv;
        Bsrc = g_xs + (size_t)tb * C_ * N_;
        Cdst = ((which == 0) ? g_q : (which == 1) ? g_k : g_v) + (size_t)tb * C_ * N_;
    } else {
        tb = z;
        A = g_wp;
        Bsrc = g_q + (size_t)tb * C_ * N_;
        kvs = g_kvs + tb * C_;
    }

    wmma::fragment<wmma::accumulator, 16, 16, 8, float> acc[2][2];
#pragma unroll
    for (int i = 0; i < 2; i++)
#pragma unroll
        for (int j = 0; j < 2; j++)
            wmma::fill_fragment(acc[i][j], 0.0f);

    for (int kt = 0; kt < C_; kt += BK) {
        // A tile: 64 rows x 32 cols (512 float4 / 128 threads = 4 each)
#pragma unroll
        for (int i = 0; i < 4; i++) {
            int idx = tid + i * 128;
            int r = idx >> 3;
            int c4 = (idx & 7) << 2;
            float4 vv = *reinterpret_cast<const float4*>(&A[(o0 + r) * C_ + kt + c4]);
            *reinterpret_cast<float4*>(&As[r * ASTR + c4]) = vv;
        }
        // B tile: 32 rows x 64 cols
#pragma unroll
        for (int i = 0; i < 4; i++) {
            int idx = tid + i * 128;
            int r = idx >> 4;
            int c4 = (idx & 15) << 2;
            float4 vv = *reinterpret_cast<const float4*>(&Bsrc[(kt + r) * N_ + n0 + c4]);
            if (MODE == 1) {
                float s = kvs[kt + r];
                vv.x *= s; vv.y *= s; vv.z *= s; vv.w *= s;
            }
            *reinterpret_cast<float4*>(&Bs[r * BSTR + c4]) = vv;
        }
        __syncthreads();

#pragma unroll
        for (int kk = 0; kk < BK; kk += 8) {
            wmma::fragment<wmma::matrix_a, 16, 16, 8, wmma::precision::tf32, wmma::row_major> af[2];
            wmma::fragment<wmma::matrix_b, 16, 16, 8, wmma::precision::tf32, wmma::row_major> bf[2];
#pragma unroll
            for (int i = 0; i < 2; i++) {
                wmma::load_matrix_sync(af[i], &As[(wr * 32 + i * 16) * ASTR + kk], ASTR);
#pragma unroll
                for (int e = 0; e < af[i].num_elements; e++)
                    af[i].x[e] = wmma::__float_to_tf32(af[i].x[e]);
            }
#pragma unroll
            for (int j = 0; j < 2; j++) {
                wmma::load_matrix_sync(bf[j], &Bs[kk * BSTR + wc * 32 + j * 16], BSTR);
#pragma unroll
                for (int e = 0; e < bf[j].num_elements; e++)
                    bf[j].x[e] = wmma::__float_to_tf32(bf[j].x[e]);
            }
#pragma unroll
            for (int i = 0; i < 2; i++)
#pragma unroll
                for (int j = 0; j < 2; j++)
                    wmma::mma_sync(acc[i][j], af[i], bf[j], acc[i][j]);
        }
        __syncthreads();
    }

    if (MODE == 0) {
#pragma unroll
        for (int i = 0; i < 2; i++)
#pragma unroll
            for (int j = 0; j < 2; j++)
                wmma::store_matrix_sync(&Cdst[(o0 + wr * 32 + i * 16) * N_ + n0 + wc * 32 + j * 16],
                                        acc[i][j], N_, wmma::mem_row_major);
    } else {
        // stage through smem, add shift + identity, write output
        float* Cs = smem;   // 64 x BSTR <= 4480 floats
#pragma unroll
        for (int i = 0; i < 2; i++)
#pragma unroll
            for (int j = 0; j < 2; j++)
                wmma::store_matrix_sync(&Cs[(wr * 32 + i * 16) * BSTR + wc * 32 + j * 16],
                                        acc[i][j], BSTR, wmma::mem_row_major);
        __syncthreads();
        const float* xid = x_identity + (size_t)tb * C_ * N_;
        float* outp = out_global + (size_t)tb * C_ * N_;
#pragma unroll
        for (int e = 0; e < 8; e++) {
            int idx = tid + e * 128;      // 0..1023 (1024 float4 = 4096 elems)
            int r = idx >> 4;
            int c4 = (idx & 15) << 2;
            int o = o0 + r;
            float4 cv = *reinterpret_cast<const float4*>(&Cs[r * BSTR + c4]);
            float4 xv = *reinterpret_cast<const float4*>(&xid[o * N_ + n0 + c4]);
            float sp = g_sp[o];
            float4 res;
            res.x = cv.x + sp + xv.x;
            res.y = cv.y + sp + xv.y;
            res.z = cv.z + sp + xv.z;
            res.w = cv.w + sp + xv.w;
            *reinterpret_cast<float4*>(&outp[o * N_ + n0 + c4]) = res;
        }
    }
}

// ---------------------------------------------------------------------------
extern "C" void kernel_launch(void* const* d_in, const int* in_sizes, int n_in,
                              void* d_out, int out_size)
{
    const float* x    = (const float*)d_in[0];
    const float* q_w  = (const float*)d_in[1];
    const float* q_g  = (const float*)d_in[2];
    const float* q_b  = (const float*)d_in[3];
    const float* q_m  = (const float*)d_in[4];
    const float* q_v  = (const float*)d_in[5];
    const float* k_w  = (const float*)d_in[6];
    const float* k_g  = (const float*)d_in[7];
    const float* k_b  = (const float*)d_in[8];
    const float* k_m  = (const float*)d_in[9];
    const float* k_v  = (const float*)d_in[10];
    const float* v_w  = (const float*)d_in[11];
    const float* v_g  = (const float*)d_in[12];
    const float* v_b  = (const float*)d_in[13];
    const float* v_m  = (const float*)d_in[14];
    const float* v_v  = (const float*)d_in[15];
    const float* p_w  = (const float*)d_in[16];
    const float* p_b  = (const float*)d_in[17];
    const float* p_g  = (const float*)d_in[18];
    const float* p_b2 = (const float*)d_in[19];
    const float* p_m  = (const float*)d_in[20];
    const float* p_v  = (const float*)d_in[21];
    float* out = (float*)d_out;

    prep_kernel<<<(C_ * C_ + 255) / 256, 256>>>(
        q_w, q_g, q_b, q_m, q_v,
        k_w, k_g, k_b, k_m, k_v,
        v_w, v_g, v_b, v_m, v_v,
        p_w, p_b, p_g, p_b2, p_m, p_v);

    lif_x_kernel<<<(S_ + 255) / 256, 256>>>(x);

    gemm_kernel<0><<<dim3(N_ / BN, C_ / BM, 3 * T_ * B_), 128>>>(nullptr, nullptr);

    lif_qkv_kernel<<<dim3((S_ + 255) / 256, 3), 256>>>();

    kv_kernel<<<(B_ * C_ * 32 + 255) / 256, 256>>>();

    gemm_kernel<1><<<dim3(N_ / BN, C_ / BM, T_ * B_), 128>>>(x, out);
}

// round 4
// speedup vs baseline: 1.0003x; 1.0002x over previous
#include <cuda_runtime.h>
#include <cuda_bf16.h>
#include <mma.h>

using namespace nvcuda;

// Problem constants
constexpr int T_ = 4;
constexpr int B_ = 16;
constexpr int C_ = 512;
constexpr int N_ = 256;                // H*W
constexpr int S_ = B_ * C_ * N_;       // per-timestep elements = 2,097,152
constexpr int TOT_ = T_ * S_;          // 8,388,608

// Scratch (device globals: allocation-free rule)
__device__ float g_wq[C_ * C_];
__device__ float g_wk[C_ * C_];
__device__ float g_wv[C_ * C_];
__device__ float g_wp[C_ * C_];
__device__ float g_sq[C_];
__device__ float g_sk[C_];
__device__ float g_sv[C_];
__device__ float g_sp[C_];
__device__ float g_xs[TOT_];
__device__ float g_q[TOT_];
__device__ float g_k[TOT_];
__device__ float g_v[TOT_];
__device__ float g_kvs[T_ * B_ * C_];

// ---------------------------------------------------------------------------
// Prep: fold BN scale into weights; compute per-channel shifts.
// ---------------------------------------------------------------------------
__global__ void prep_kernel(
    const float* __restrict__ qw, const float* __restrict__ qg, const float* __restrict__ qb,
    const float* __restrict__ qm, const float* __restrict__ qvv,
    const float* __restrict__ kw, const float* __restrict__ kg, const float* __restrict__ kb,
    const float* __restrict__ km, const float* __restrict__ kvv,
    const float* __restrict__ vw, const float* __restrict__ vg, const float* __restrict__ vb,
    const float* __restrict__ vm, const float* __restrict__ vvv,
    const float* __restrict__ pw, const float* __restrict__ pb, const float* __restrict__ pg,
    const float* __restrict__ pb2, const float* __restrict__ pm, const float* __restrict__ pvv)
{
    int idx = blockIdx.x * blockDim.x + threadIdx.x;
    if (idx >= C_ * C_) return;
    int o = idx >> 9;
    float invq = qg[o] / sqrtf(qvv[o] + 1e-5f);
    float invk = kg[o] / sqrtf(kvv[o] + 1e-5f);
    float invv = vg[o] / sqrtf(vvv[o] + 1e-5f);
    float invp = pg[o] / sqrtf(pvv[o] + 1e-5f);
    g_wq[idx] = qw[idx] * invq;
    g_wk[idx] = kw[idx] * invk;
    g_wv[idx] = vw[idx] * invv;
    g_wp[idx] = pw[idx] * invp;
    if ((idx & 511) == 0) {
        g_sq[o] = qb[o] - qm[o] * invq;
        g_sk[o] = kb[o] - km[o] * invk;
        g_sv[o] = vb[o] - vm[o] * invv;
        g_sp[o] = (pb[o] - pm[o]) * invp + pb2[o];
    }
}

// ---------------------------------------------------------------------------
// LIF on input x -> binary spikes xs.  v' = v + (x - v)/2; s = v'>=1; reset.
// ---------------------------------------------------------------------------
__global__ void lif_x_kernel(const float* __restrict__ x)
{
    int i = blockIdx.x * blockDim.x + threadIdx.x;
    if (i >= S_) return;
    float v = 0.f;
#pragma unroll
    for (int t = 0; t < T_; t++) {
        float xv = x[t * S_ + i];
        v = v + (xv - v) * 0.5f;
        float s = (v >= 1.0f) ? 1.f : 0.f;
        g_xs[t * S_ + i] = s;
        v = v * (1.f - s);
    }
}

// ---------------------------------------------------------------------------
// LIF on q/k/v pre-activations (+ folded BN shift), in place -> spikes.
// ---------------------------------------------------------------------------
__global__ void lif_qkv_kernel()
{
    int i = blockIdx.x * blockDim.x + threadIdx.x;
    if (i >= S_) return;
    int which = blockIdx.y;
    float* buf = (which == 0) ? g_q : (which == 1) ? g_k : g_v;
    const float* sh = (which == 0) ? g_sq : (which == 1) ? g_sk : g_sv;
    int c = (i >> 8) & (C_ - 1);   // i = b*C*N + c*N + n, N=256
    float shift = sh[c];
    float v = 0.f;
#pragma unroll
    for (int t = 0; t < T_; t++) {
        float pre = buf[t * S_ + i] + shift;
        v = v + (pre - v) * 0.5f;
        float s = (v >= 1.0f) ? 1.f : 0.f;
        buf[t * S_ + i] = s;
        v = v * (1.f - s);
    }
}

// ---------------------------------------------------------------------------
// kv = sum_n k*v per (t,b,c)  (exact integers), then LIF with v_th=0.5.
// One warp per (b,c); sequential over t.
// ---------------------------------------------------------------------------
__global__ void kv_kernel()
{
    int gw = (blockIdx.x * blockDim.x + threadIdx.x) >> 5;
    int lane = threadIdx.x & 31;
    if (gw >= B_ * C_) return;      // gw = b*C + c
    float v = 0.f;
#pragma unroll
    for (int t = 0; t < T_; t++) {
        const float* kp = g_k + t * S_ + gw * N_;
        const float* vp = g_v + t * S_ + gw * N_;
        float sum = 0.f;
#pragma unroll
        for (int j = 0; j < N_ / 32; j++)
            sum += kp[lane + j * 32] * vp[lane + j * 32];
#pragma unroll
        for (int off = 16; off > 0; off >>= 1)
            sum += __shfl_xor_sync(0xFFFFFFFFu, sum, off);
        v = v + (sum - v) * 0.5f;
        float s = (v >= 0.5f) ? 1.f : 0.f;
        if (lane == 0) g_kvs[t * B_ * C_ + gw] = s;
        v = v * (1.f - s);
    }
}

// ---------------------------------------------------------------------------
// tf32 wmma GEMM: Y[o][n] = sum_c A[o][c] * X[c][n]
// MODE 0: A in {g_wq,g_wk,g_wv} (z = which*64 + tb), X = xs, out raw to g_q/g_k/g_v
// MODE 1: A = g_wp, X = q * kvs (attn, built in the loader),
//         epilogue adds g_sp[o] + identity, writes d_out.
// Tile: 64x64x32, 4 warps (each 32x32 via 2x2 m16n16k8 fragments).
// ---------------------------------------------------------------------------
constexpr int BM = 64, BN = 64, BK = 32;
constexpr int ASTR = BK + 4;   // 36
constexpr int BSTR = BN + 4;   // 68

template <int MODE>
__global__ void __launch_bounds__(128) gemm_kernel(const float* __restrict__ x_identity,
                                                   float* __restrict__ out_global)
{
    __shared__ float smem[BM * ASTR + BK * BSTR];   // 4480 floats
    float* As = smem;
    float* Bs = smem + BM * ASTR;

    int tid = threadIdx.x;
    int warp = tid >> 5;
    int wr = warp >> 1, wc = warp & 1;
    int n0 = blockIdx.x * BN;
    int o0 = blockIdx.y * BM;
    int z = blockIdx.z;

    const float* A;
    const float* Bsrc;
    float* Cdst = nullptr;
    const float* kvs = nullptr;
    int tb;
    if (MODE == 0) {
        int which = z >> 6;
        tb = z & 63;
        A = (which == 0) ? g_wq : (which == 1) ? g_wk : g_wv;
        Bsrc = g_xs + (size_t)tb * C_ * N_;
        Cdst = ((which == 0) ? g_q : (which == 1) ? g_k : g_v) + (size_t)tb * C_ * N_;
    } else {
        tb = z;
        A = g_wp;
        Bsrc = g_q + (size_t)tb * C_ * N_;
        kvs = g_kvs + tb * C_;
    }

    wmma::fragment<wmma::accumulator, 16, 16, 8, float> acc[2][2];
#pragma unroll
    for (int i = 0; i < 2; i++)
#pragma unroll
        for (int j = 0; j < 2; j++)
            wmma::fill_fragment(acc[i][j], 0.0f);

    for (int kt = 0; kt < C_; kt += BK) {
        // A tile: 64 rows x 32 cols (512 float4 / 128 threads = 4 each)
#pragma unroll
        for (int i = 0; i < 4; i++) {
            int idx = tid + i * 128;
            int r = idx >> 3;
            int c4 = (idx & 7) << 2;
            float4 vv = *reinterpret_cast<const float4*>(&A[(o0 + r) * C_ + kt + c4]);
            *reinterpret_cast<float4*>(&As[r * ASTR + c4]) = vv;
        }
        // B tile: 32 rows x 64 cols
#pragma unroll
        for (int i = 0; i < 4; i++) {
            int idx = tid + i * 128;
            int r = idx >> 4;
            int c4 = (idx & 15) << 2;
            float4 vv = *reinterpret_cast<const float4*>(&Bsrc[(kt + r) * N_ + n0 + c4]);
            if (MODE == 1) {
                float s = kvs[kt + r];
                vv.x *= s; vv.y *= s; vv.z *= s; vv.w *= s;
            }
            *reinterpret_cast<float4*>(&Bs[r * BSTR + c4]) = vv;
        }
        __syncthreads();

#pragma unroll
        for (int kk = 0; kk < BK; kk += 8) {
            wmma::fragment<wmma::matrix_a, 16, 16, 8, wmma::precision::tf32, wmma::row_major> af[2];
            wmma::fragment<wmma::matrix_b, 16, 16, 8, wmma::precision::tf32, wmma::row_major> bf[2];
#pragma unroll
            for (int i = 0; i < 2; i++) {
                wmma::load_matrix_sync(af[i], &As[(wr * 32 + i * 16) * ASTR + kk], ASTR);
#pragma unroll
                for (int e = 0; e < af[i].num_elements; e++)
                    af[i].x[e] = wmma::__float_to_tf32(af[i].x[e]);
            }
#pragma unroll
            for (int j = 0; j < 2; j++) {
                wmma::load_matrix_sync(bf[j], &Bs[kk * BSTR + wc * 32 + j * 16], BSTR);
#pragma unroll
                for (int e = 0; e < bf[j].num_elements; e++)
                    bf[j].x[e] = wmma::__float_to_tf32(bf[j].x[e]);
            }
#pragma unroll
            for (int i = 0; i < 2; i++)
#pragma unroll
                for (int j = 0; j < 2; j++)
                    wmma::mma_sync(acc[i][j], af[i], bf[j], acc[i][j]);
        }
        __syncthreads();
    }

    if (MODE == 0) {
#pragma unroll
        for (int i = 0; i < 2; i++)
#pragma unroll
            for (int j = 0; j < 2; j++)
                wmma::store_matrix_sync(&Cdst[(o0 + wr * 32 + i * 16) * N_ + n0 + wc * 32 + j * 16],
                                        acc[i][j], N_, wmma::mem_row_major);
    } else {
        // stage through smem, add shift + identity, write output
        float* Cs = smem;   // 64 x BSTR <= 4480 floats
#pragma unroll
        for (int i = 0; i < 2; i++)
#pragma unroll
            for (int j = 0; j < 2; j++)
                wmma::store_matrix_sync(&Cs[(wr * 32 + i * 16) * BSTR + wc * 32 + j * 16],
                                        acc[i][j], BSTR, wmma::mem_row_major);
        __syncthreads();
        const float* xid = x_identity + (size_t)tb * C_ * N_;
        float* outp = out_global + (size_t)tb * C_ * N_;
#pragma unroll
        for (int e = 0; e < 8; e++) {
            int idx = tid + e * 128;      // 0..1023 (1024 float4 = 4096 elems)
            int r = idx >> 4;
            int c4 = (idx & 15) << 2;
            int o = o0 + r;
            float4 cv = *reinterpret_cast<const float4*>(&Cs[r * BSTR + c4]);
            float4 xv = *reinterpret_cast<const float4*>(&xid[o * N_ + n0 + c4]);
            float sp = g_sp[o];
            float4 res;
            res.x = cv.x + sp + xv.x;
            res.y = cv.y + sp + xv.y;
            res.z = cv.z + sp + xv.z;
            res.w = cv.w + sp + xv.w;
            *reinterpret_cast<float4*>(&outp[o * N_ + n0 + c4]) = res;
        }
    }
}

// ---------------------------------------------------------------------------
extern "C" void kernel_launch(void* const* d_in, const int* in_sizes, int n_in,
                              void* d_out, int out_size)
{
    const float* x    = (const float*)d_in[0];
    const float* q_w  = (const float*)d_in[1];
    const float* q_g  = (const float*)d_in[2];
    const float* q_b  = (const float*)d_in[3];
    const float* q_m  = (const float*)d_in[4];
    const float* q_v  = (const float*)d_in[5];
    const float* k_w  = (const float*)d_in[6];
    const float* k_g  = (const float*)d_in[7];
    const float* k_b  = (const float*)d_in[8];
    const float* k_m  = (const float*)d_in[9];
    const float* k_v  = (const float*)d_in[10];
    const float* v_w  = (const float*)d_in[11];
    const float* v_g  = (const float*)d_in[12];
    const float* v_b  = (const float*)d_in[13];
    const float* v_m  = (const float*)d_in[14];
    const float* v_v  = (const float*)d_in[15];
    const float* p_w  = (const float*)d_in[16];
    const float* p_b  = (const float*)d_in[17];
    const float* p_g  = (const float*)d_in[18];
    const float* p_b2 = (const float*)d_in[19];
    const float* p_m  = (const float*)d_in[20];
    const float* p_v  = (const float*)d_in[21];
    float* out = (float*)d_out;

    prep_kernel<<<(C_ * C_ + 255) / 256, 256>>>(
        q_w, q_g, q_b, q_m, q_v,
        k_w, k_g, k_b, k_m, k_v,
        v_w, v_g, v_b, v_m, v_v,
        p_w, p_b, p_g, p_b2, p_m, p_v);

    lif_x_kernel<<<(S_ + 255) / 256, 256>>>(x);

    gemm_kernel<0><<<dim3(N_ / BN, C_ / BM, 3 * T_ * B_), 128>>>(nullptr, nullptr);

    lif_qkv_kernel<<<dim3((S_ + 255) / 256, 3), 256>>>();

    kv_kernel<<<(B_ * C_ * 32 + 255) / 256, 256>>>();

    gemm_kernel<1><<<dim3(N_ / BN, C_ / BM, T_ * B_), 128>>>(x, out);
}